// round 17
// baseline (speedup 1.0000x reference)
#include <cuda_runtime.h>
#include <cuda_fp16.h>
#include <cuda_fp8.h>
#include <math.h>

#define NN 50000
#define EE 1600000
#define BB 4
#define FF 16
#define HH 16
#define BF 64   // BB*FF values per node row
#define CC 10
#define CAP 96  // padded CSR bucket size
#define FSC 16.0f  // fp8 pre-scale

// ---------------- device scratch ----------------
__device__ uint4 g_bufA[NN * 8];    // z   (unscaled, fp16, 128B/row)
__device__ uint2 g_bufAs[NN * 8];   // FSC*dinv*z (fp8 e4m3, 64B/row)
__device__ uint4 g_bufB[NN * 8];
__device__ uint2 g_bufBs[NN * 8];
__device__ uint2 g_t1[NN * 8];      // scaled-domain prop1 out (fp8)
__device__ uint4 g_t2[NN * 8];      // scaled-domain prop2 out (fp16)
__device__ unsigned short g_csr[NN * CAP + 32]; // +32 pad for batch prefetch
__device__ int   g_wp[NN];          // bucket fill = in-degree
__device__ int   g_deg[NN];         // out-degree
__device__ float g_dinv[NN];        // FSC * dinv
__device__ float g_dinv2[NN];       // true dinv^2
__device__ float g_rdinv[NN];       // sqrt(deg)/FSC
__device__ float g_pool[BF];

__device__ __forceinline__ float elu1(float x) {
    return x > 0.0f ? x : expm1f(x);
}
__device__ __forceinline__ __half2 fp8x2_to_h2(unsigned short u) {
    __half2_raw r = __nv_cvt_fp8x2_to_halfraw2((__nv_fp8x2_storage_t)u, __NV_E4M3);
    return *reinterpret_cast<__half2*>(&r);
}
__device__ __forceinline__ unsigned short f2_to_fp8x2(float x, float y) {
    float2 f; f.x = x; f.y = y;
    return (unsigned short)__nv_cvt_float2_to_fp8x2(f, __NV_SATFINITE, __NV_E4M3);
}
__device__ __forceinline__ unsigned short h2_to_fp8x2(__half2 h) {
    return (unsigned short)__nv_cvt_halfraw2_to_fp8x2(*reinterpret_cast<__half2_raw*>(&h),
                                                      __NV_SATFINITE, __NV_E4M3);
}
__device__ __forceinline__ __half2 shfl_xor_h2(__half2 v, int m) {
    unsigned u = __shfl_xor_sync(0xffffffffu, *reinterpret_cast<unsigned*>(&v), m);
    return *reinterpret_cast<__half2*>(&u);
}

// accumulate one 8-byte fp8 slice (4x fp8x2) into 4 half2 banks
#define ACC8(v, X0, X1, X2, X3) \
    X0 = __hadd2(X0, fp8x2_to_h2((unsigned short)((v).x)));        \
    X1 = __hadd2(X1, fp8x2_to_h2((unsigned short)((v).x >> 16)));  \
    X2 = __hadd2(X2, fp8x2_to_h2((unsigned short)((v).y)));        \
    X3 = __hadd2(X3, fp8x2_to_h2((unsigned short)((v).y >> 16)));

// ---------------- transpose x [B,F,N] fp32 -> [N,64] fp16 + init -----------
__global__ void k_transpose(const float* __restrict__ x, __half* __restrict__ dst) {
    int flat = (blockIdx.y * gridDim.x + blockIdx.x) * 256 + threadIdx.y * 32 + threadIdx.x;
    if (flat < NN) { g_wp[flat] = 0; g_deg[flat] = 0; }

    __shared__ float tile[32][33];
    int n0 = blockIdx.x * 32;
    int bf0 = blockIdx.y * 32;
    int tx = threadIdx.x;
    int ty = threadIdx.y;
    #pragma unroll
    for (int i = ty; i < 32; i += 8) {
        int n = n0 + tx;
        tile[i][tx] = (n < NN) ? x[(bf0 + i) * NN + n] : 0.0f;
    }
    __syncthreads();
    #pragma unroll
    for (int i = ty; i < 32; i += 8) {
        int n = n0 + i;
        if (n < NN) dst[n * BF + bf0 + tx] = __float2half_rn(tile[tx][i]);
    }
}

// ---------------- fused: deg RED + bucket scatter --------------------------
__global__ void k_fuse(const int* __restrict__ ei) {
    int e = blockIdx.x * 256 + threadIdx.x;
    if (e >= EE) return;
    int s = ei[e];
    int d = ei[EE + e];
    atomicAdd(&g_deg[s], 1);
    int pos = atomicAdd(&g_wp[d], 1);
    g_csr[d * CAP + pos] = (unsigned short)s;
}

// ---------------- dinv consts + scaled fp8 input buffer --------------------
__global__ void k_dinvscale(const uint4* __restrict__ z, uint2* __restrict__ zs) {
    int t = blockIdx.x * 256 + threadIdx.x;
    if (t < BF) g_pool[t] = 0.0f;
    if (t >= NN * 8) return;
    int n = t >> 3;
    int c = t & 7;
    int d = g_deg[n];
    float di = (d > 0) ? rsqrtf((float)d) : 0.0f;
    if (c == 0) {
        g_dinv[n] = FSC * di;
        g_dinv2[n] = di * di;
        g_rdinv[n] = (d > 0) ? (sqrtf((float)d) * (1.0f / FSC)) : 0.0f;
    }
    __half2 dh = __float2half2_rn(FSC * di);
    uint4 v = z[t];
    __half2 m0 = __hmul2(dh, *(__half2*)&v.x);
    __half2 m1 = __hmul2(dh, *(__half2*)&v.y);
    __half2 m2 = __hmul2(dh, *(__half2*)&v.z);
    __half2 m3 = __hmul2(dh, *(__half2*)&v.w);
    uint2 r;
    r.x = (unsigned)h2_to_fp8x2(m0) | ((unsigned)h2_to_fp8x2(m1) << 16);
    r.y = (unsigned)h2_to_fp8x2(m2) | ((unsigned)h2_to_fp8x2(m3) << 16);
    zs[t] = r;
}

// ---------------- sparse prop: fp8 gathered rows, weight-free sums ---------
// out_s[n,:] = -dinv2[n] * sum_{e->n} in_s[src_e,:]
// warp per dst node; 4 groups x 8 lanes; lane = 8B slice of the 64B fp8 row.
// Indices loaded COALESCED once per 32-edge batch (2 sectors warp-wide),
// distributed to groups via shuffles (no L1 sectors). Double-buffered.
// OUT8: store fp8 (64B row) else fp16 (128B row).
template<int OUT8>
__global__ __launch_bounds__(256) void k_prop(const unsigned char* __restrict__ in,
                                              void* __restrict__ out) {
    int w = (blockIdx.x * 256 + threadIdx.x) >> 5;
    int lane = threadIdx.x & 31;
    if (w >= NN) return;
    int g = lane >> 3;             // edge-group 0..3
    int q = lane & 7;              // 8B slice 0..7
    const unsigned char* base = in + q * 8;
    int len = g_wp[w];
    float negd2 = -g_dinv2[w];
    int full = len >> 2;           // unchecked 4-edge steps
    int rem = len & 3;

    const __half2 z2 = __float2half2_rn(0.0f);
    __half2 A0 = z2, A1 = z2, A2 = z2, A3 = z2;
    __half2 B0 = z2, B1 = z2, B2 = z2, B3 = z2;

    int lanebase = w * CAP + lane;
    unsigned idx  = __ldg(&g_csr[lanebase]);        // batch 0 (edges 0..31)
    unsigned idxn = __ldg(&g_csr[lanebase + 32]);   // batch 1 prefetch
    int t = 0;
    int nb = 64;
    // whole 32-edge batches (8 steps)
    while (t + 8 <= full) {
        #pragma unroll
        for (int u = 0; u < 8; u += 2) {
            unsigned s0 = __shfl_sync(0xffffffffu, idx, u * 4 + g);
            unsigned s1 = __shfl_sync(0xffffffffu, idx, u * 4 + 4 + g);
            uint2 v0 = *(const uint2*)(base + s0 * 64);
            uint2 v1 = *(const uint2*)(base + s1 * 64);
            ACC8(v0, A0, A1, A2, A3);
            ACC8(v1, B0, B1, B2, B3);
        }
        t += 8;
        idx = idxn;
        idxn = __ldg(&g_csr[lanebase + nb]);        // padded; unused if done
        nb += 32;
    }
    // leftover full steps within current batch (u = local step, 0-based)
    int u = 0;
    for (; t + 2 <= full; t += 2, u += 2) {
        unsigned s0 = __shfl_sync(0xffffffffu, idx, u * 4 + g);
        unsigned s1 = __shfl_sync(0xffffffffu, idx, u * 4 + 4 + g);
        uint2 v0 = *(const uint2*)(base + s0 * 64);
        uint2 v1 = *(const uint2*)(base + s1 * 64);
        ACC8(v0, A0, A1, A2, A3);
        ACC8(v1, B0, B1, B2, B3);
    }
    if (t < full) {
        unsigned s0 = __shfl_sync(0xffffffffu, idx, u * 4 + g);
        uint2 v = *(const uint2*)(base + s0 * 64);
        ACC8(v, A0, A1, A2, A3);
        u++;
    }
    {
        unsigned st = __shfl_sync(0xffffffffu, idx, u * 4 + g);  // uniform shuffle
        if (g < rem) {
            uint2 v = *(const uint2*)(base + st * 64);
            ACC8(v, B0, B1, B2, B3);
        }
    }

    // bank combine + cross-group reduce, all in half2
    __half2 S0 = __hadd2(A0, B0);
    __half2 S1 = __hadd2(A1, B1);
    __half2 S2 = __hadd2(A2, B2);
    __half2 S3 = __hadd2(A3, B3);
    S0 = __hadd2(S0, shfl_xor_h2(S0, 8));  S0 = __hadd2(S0, shfl_xor_h2(S0, 16));
    S1 = __hadd2(S1, shfl_xor_h2(S1, 8));  S1 = __hadd2(S1, shfl_xor_h2(S1, 16));
    S2 = __hadd2(S2, shfl_xor_h2(S2, 8));  S2 = __hadd2(S2, shfl_xor_h2(S2, 16));
    S3 = __hadd2(S3, shfl_xor_h2(S3, 8));  S3 = __hadd2(S3, shfl_xor_h2(S3, 16));

    if (g == 0) {
        __half2 sc = __float2half2_rn(negd2);
        S0 = __hmul2(sc, S0);
        S1 = __hmul2(sc, S1);
        S2 = __hmul2(sc, S2);
        S3 = __hmul2(sc, S3);
        if (OUT8) {
            uint2 r;
            r.x = (unsigned)h2_to_fp8x2(S0) | ((unsigned)h2_to_fp8x2(S1) << 16);
            r.y = (unsigned)h2_to_fp8x2(S2) | ((unsigned)h2_to_fp8x2(S3) << 16);
            *(uint2*)((unsigned char*)out + w * 64 + q * 8) = r;
        } else {
            uint4 r;
            r.x = *(unsigned*)&S0; r.y = *(unsigned*)&S1;
            r.z = *(unsigned*)&S2; r.w = *(unsigned*)&S3;
            *(uint4*)((char*)out + w * 128 + q * 16) = r;
        }
    }
}

// ---------------- dense ----------------------------------------------------
__device__ __forceinline__ void unpack8(uint4 v, float* a) {
    float2 f;
    f = __half22float2(*(__half2*)&v.x); a[0] = f.x; a[1] = f.y;
    f = __half22float2(*(__half2*)&v.y); a[2] = f.x; a[3] = f.y;
    f = __half22float2(*(__half2*)&v.z); a[4] = f.x; a[5] = f.y;
    f = __half22float2(*(__half2*)&v.w); a[6] = f.x; a[7] = f.y;
}
__device__ __forceinline__ void unpack8f8(unsigned lo, unsigned hi, float* a) {
    float2 f;
    f = __half22float2(fp8x2_to_h2((unsigned short)lo));         a[0] = f.x; a[1] = f.y;
    f = __half22float2(fp8x2_to_h2((unsigned short)(lo >> 16))); a[2] = f.x; a[3] = f.y;
    f = __half22float2(fp8x2_to_h2((unsigned short)hi));         a[4] = f.x; a[5] = f.y;
    f = __half22float2(fp8x2_to_h2((unsigned short)(hi >> 16))); a[6] = f.x; a[7] = f.y;
}

template<int WS>
__global__ __launch_bounds__(256) void k_dense(const __half* __restrict__ z,
                                               const unsigned char* __restrict__ t1s,
                                               const __half* __restrict__ t2s,
                                               const float* __restrict__ W,
                                               const float* __restrict__ bias,
                                               __half* __restrict__ out,
                                               unsigned char* __restrict__ outs) {
    __shared__ float sW[48 * 16];
    __shared__ float sB[16];
    int tid = threadIdx.x;
    for (int j = tid; j < 768; j += 256) {
        int kf = j >> 4;
        int o = j & 15;
        int k = kf >> 4;
        int f = kf & 15;
        sW[j] = W[k * 256 + o * 16 + f];
    }
    if (tid < 16) sB[tid] = bias[tid];
    __syncthreads();

    int r = blockIdx.x * 256 + tid;
    if (r >= NN * BB) return;
    int n = r >> 2;
    float rd = g_rdinv[n];

    float a[48];
    {
        const uint4* p0 = (const uint4*)(z + r * 16);
        uint4 q1 = *(const uint4*)(t1s + r * 16);   // 16 fp8
        const uint4* p2 = (const uint4*)(t2s + r * 16);
        unpack8(p0[0], a);      unpack8(p0[1], a + 8);
        unpack8f8(q1.x, q1.y, a + 16);
        unpack8f8(q1.z, q1.w, a + 24);
        unpack8(p2[0], a + 32); unpack8(p2[1], a + 40);
        float rd2 = 2.0f * rd;
        #pragma unroll
        for (int i = 0; i < 16; i++) {
            a[16 + i] *= rd;                          // Tx1 true
            a[32 + i] = fmaf(rd2, a[32 + i], -a[i]);  // 2*Tx2true - z
        }
    }
    float acc[16];
    #pragma unroll
    for (int o = 0; o < 16; o++) acc[o] = sB[o];
    #pragma unroll
    for (int kk = 0; kk < 48; kk++) {
        float av = a[kk];
        const float4* w4 = (const float4*)(sW + kk * 16);
        #pragma unroll
        for (int qq = 0; qq < 4; qq++) {
            float4 w = w4[qq];
            acc[qq * 4 + 0] = fmaf(av, w.x, acc[qq * 4 + 0]);
            acc[qq * 4 + 1] = fmaf(av, w.y, acc[qq * 4 + 1]);
            acc[qq * 4 + 2] = fmaf(av, w.z, acc[qq * 4 + 2]);
            acc[qq * 4 + 3] = fmaf(av, w.w, acc[qq * 4 + 3]);
        }
    }
    float h[16];
    #pragma unroll
    for (int i = 0; i < 16; i++) h[i] = elu1(acc[i]);

    uint4 o0, o1;
    {
        unsigned* po = (unsigned*)&o0;
        unsigned* po1 = (unsigned*)&o1;
        #pragma unroll
        for (int qq = 0; qq < 4; qq++) {
            __half2 hh = __floats2half2_rn(h[qq * 2 + 0], h[qq * 2 + 1]);
            po[qq] = *(unsigned*)&hh;
            __half2 hh2 = __floats2half2_rn(h[8 + qq * 2 + 0], h[8 + qq * 2 + 1]);
            po1[qq] = *(unsigned*)&hh2;
        }
    }
    uint4* dst = (uint4*)(out + r * 16);
    dst[0] = o0;
    dst[1] = o1;

    if (WS) {
        float di = g_dinv[n];    // = FSC * dinv
        uint4 s;
        s.x = (unsigned)f2_to_fp8x2(di * h[0],  di * h[1])
            | ((unsigned)f2_to_fp8x2(di * h[2],  di * h[3]) << 16);
        s.y = (unsigned)f2_to_fp8x2(di * h[4],  di * h[5])
            | ((unsigned)f2_to_fp8x2(di * h[6],  di * h[7]) << 16);
        s.z = (unsigned)f2_to_fp8x2(di * h[8],  di * h[9])
            | ((unsigned)f2_to_fp8x2(di * h[10], di * h[11]) << 16);
        s.w = (unsigned)f2_to_fp8x2(di * h[12], di * h[13])
            | ((unsigned)f2_to_fp8x2(di * h[14], di * h[15]) << 16);
        *(uint4*)(outs + r * 16) = s;
    }
}

// ---------------- mean pool (fp16 in, fp32 accum) --------------------------
__global__ void k_pool(const __half2* __restrict__ h) {
    int tid = blockIdx.x * blockDim.x + threadIdx.x;
    int c = tid & 31;
    int grp = tid >> 5;
    int ngrp = (gridDim.x * blockDim.x) >> 5;
    float sx = 0.0f, sy = 0.0f;
    for (int n = grp; n < NN; n += ngrp) {
        float2 v = __half22float2(h[n * 32 + c]);
        sx += v.x; sy += v.y;
    }
    atomicAdd(&g_pool[2 * c], sx);
    atomicAdd(&g_pool[2 * c + 1], sy);
}

// ---------------- head ----------------
__global__ void k_head(const float* __restrict__ lw, const float* __restrict__ lb,
                       float* __restrict__ out) {
    __shared__ float gsh[BF];
    __shared__ float lg[BB * CC];
    int tid = threadIdx.x;
    if (tid < BF) gsh[tid] = g_pool[tid] * (1.0f / (float)NN);
    __syncthreads();
    if (tid < BB * CC) {
        int b = tid / CC, c = tid % CC;
        float s = lb[c];
        #pragma unroll
        for (int hh = 0; hh < HH; hh++) s += gsh[b * HH + hh] * lw[c * HH + hh];
        lg[tid] = s;
    }
    __syncthreads();
    if (tid < BB * CC) {
        int b = tid / CC;
        float mx = -1e30f;
        for (int c2 = 0; c2 < CC; c2++) mx = fmaxf(mx, lg[b * CC + c2]);
        float se = 0.0f;
        for (int c2 = 0; c2 < CC; c2++) se += expf(lg[b * CC + c2] - mx);
        out[tid] = lg[tid] - mx - logf(se);
    }
}

// ---------------- launcher ----------------
extern "C" void kernel_launch(void* const* d_in, const int* in_sizes, int n_in,
                              void* d_out, int out_size) {
    const float* x  = (const float*)d_in[0];
    const int* ei   = (const int*)d_in[1];   // JAX x64 disabled -> int32
    const float* W1 = (const float*)d_in[2];
    const float* b1 = (const float*)d_in[3];
    const float* W2 = (const float*)d_in[4];
    const float* b2 = (const float*)d_in[5];
    const float* W3 = (const float*)d_in[6];
    const float* b3 = (const float*)d_in[7];
    const float* lw = (const float*)d_in[8];
    const float* lb = (const float*)d_in[9];
    float* out = (float*)d_out;

    __half *bufA, *bufB;
    unsigned char *bufAs, *bufBs, *t1;
    __half *t2;
    cudaGetSymbolAddress((void**)&bufA, g_bufA);
    cudaGetSymbolAddress((void**)&bufAs, g_bufAs);
    cudaGetSymbolAddress((void**)&bufB, g_bufB);
    cudaGetSymbolAddress((void**)&bufBs, g_bufBs);
    cudaGetSymbolAddress((void**)&t1, g_t1);
    cudaGetSymbolAddress((void**)&t2, g_t2);

    const int EB = (EE + 255) / 256;
    const int PB = NN / 8;
    const int DB = (NN * BB + 255) / 256;
    const int SB2 = (NN * 8 + 255) / 256;

    dim3 tb(32, 8);
    dim3 tg((NN + 31) / 32, 2);
    k_transpose<<<tg, tb>>>(x, bufA);                             // 1
    k_fuse<<<EB, 256>>>(ei);                                      // 2
    k_dinvscale<<<SB2, 256>>>((const uint4*)bufA, (uint2*)bufAs); // 3

    // layer 1
    k_prop<1><<<PB, 256>>>(bufAs, t1);                            // 4 <- ncu window
    k_prop<0><<<PB, 256>>>(t1, t2);
    k_dense<1><<<DB, 256>>>(bufA, t1, t2, W1, b1, bufB, bufBs);
    // layer 2
    k_prop<1><<<PB, 256>>>(bufBs, t1);
    k_prop<0><<<PB, 256>>>(t1, t2);
    k_dense<1><<<DB, 256>>>(bufB, t1, t2, W2, b2, bufA, bufAs);
    // layer 3
    k_prop<1><<<PB, 256>>>(bufAs, t1);
    k_prop<0><<<PB, 256>>>(t1, t2);
    k_dense<0><<<DB, 256>>>(bufA, t1, t2, W3, b3, bufB, (unsigned char*)nullptr);

    k_pool<<<256, 256>>>((const __half2*)bufB);
    k_head<<<1, 64>>>(lw, lb, out);
}